// round 14
// baseline (speedup 1.0000x reference)
#include <cuda_runtime.h>
#include <cuda_fp16.h>
#include <math.h>
#include <stdint.h>

// Problem constants
#define TOK 4096          // B * L = 2 * 2048
#define CDIM 384
#define LSEQ 2048
#define DSTATE 16
#define DTRANK 24
#define NCHUNK 32
#define CLEN 64           // LSEQ / NCHUNK

// ---------------- scratch (no cudaMalloc allowed) ----------------
__device__ float g_xz [TOK*768];
__device__ float g_xc [TOK*CDIM];
__device__ float g_xcT[CDIM*TOK];
__device__ float g_dbcT[64*TOK];       // transposed: rows 0..31 = B(s), 32..63 = C(s)
__device__ float g_dtT[CDIM*TOK];      // dt transposed [d][tok], fp32 (feeds exp)
__device__ float g_y  [TOK*CDIM];
__device__ float g_x1 [TOK*CDIM];
__device__ float g_wT [27*CDIM];
// half activations (GEMM A operands)
__device__ __half g_hln_h[TOK*CDIM];
__device__ __half g_xc_h [TOK*CDIM];
__device__ __half g_y2_h [TOK*CDIM];
__device__ __half g_h2_h [TOK*CDIM];
__device__ __half g_t1_h [TOK*CDIM];
// half transposed weights [N][K=384], K-major
__device__ __half g_winT [768*CDIM];
__device__ __half g_wcatT[448*CDIM];   // rows 0..63: wxp (B/C proj); rows 64..447: wcomb (dt)
__device__ __half g_woutT[CDIM*CDIM];
__device__ __half g_w1T  [CDIM*CDIM];
__device__ __half g_w2T  [CDIM*CDIM];
// chunked-scan state: [bd(768)][chunk(32)][s(16)]
__device__ float g_P [768*NCHUNK*DSTATE];
__device__ float g_S [768*NCHUNK*DSTATE];
__device__ float g_hs[768*NCHUNK*DSTATE];

// ---------------- math helpers ----------------
__device__ __forceinline__ float siluf(float x){ return x / (1.f + __expf(-x)); }
__device__ __forceinline__ float geluf(float x){
    float x3 = x*x*x;
    return 0.5f*x*(1.f + tanhf(0.7978845608028654f*(x + 0.044715f*x3)));
}
__device__ __forceinline__ float softplusf(float x){
    return fmaxf(x, 0.f) + log1pf(__expf(-fabsf(x)));
}
__device__ __forceinline__ uint32_t smem_u32(const void* p){
    uint32_t a;
    asm("{ .reg .u64 t; cvta.to.shared.u64 t, %1; cvt.u32.u64 %0, t; }" : "=r"(a) : "l"(p));
    return a;
}
__device__ __forceinline__ void cp16(uint32_t saddr, const void* g){
    asm volatile("cp.async.cg.shared.global [%0], [%1], 16;" :: "r"(saddr), "l"(g));
}
#define CP_COMMIT() asm volatile("cp.async.commit_group;")
#define CP_WAIT(n)  asm volatile("cp.async.wait_group %0;" :: "n"(n))

// ---------------- LayerNorm over C=384 (half output for GEMM A) ----------------
__global__ void ln_kernel(const float* __restrict__ x, const float* __restrict__ gw,
                          const float* __restrict__ bw, __half* __restrict__ out){
    int row = blockIdx.x;
    int tid = threadIdx.x;
    const float* xr = x + (size_t)row*CDIM;
    float v0 = xr[tid], v1 = xr[tid+128], v2 = xr[tid+256];
    float s = v0+v1+v2;
    float q = v0*v0 + v1*v1 + v2*v2;
    #pragma unroll
    for (int m = 16; m; m >>= 1){
        s += __shfl_xor_sync(0xffffffffu, s, m);
        q += __shfl_xor_sync(0xffffffffu, q, m);
    }
    __shared__ float red[8];
    if ((tid & 31) == 0){ red[tid>>5] = s; red[4 + (tid>>5)] = q; }
    __syncthreads();
    s = red[0]+red[1]+red[2]+red[3];
    q = red[4]+red[5]+red[6]+red[7];
    float mean = s * (1.f/CDIM);
    float var  = q * (1.f/CDIM) - mean*mean;
    float r = rsqrtf(var + 1e-6f);
    __half* orow = out + (size_t)row*CDIM;
    orow[tid]     = __float2half((v0-mean)*r*gw[tid]     + bw[tid]);
    orow[tid+128] = __float2half((v1-mean)*r*gw[tid+128] + bw[tid+128]);
    orow[tid+256] = __float2half((v2-mean)*r*gw[tid+256] + bw[tid+256]);
}

__global__ void ln_gate_kernel(const float* __restrict__ y, const float* __restrict__ xz,
                               const float* __restrict__ gw, const float* __restrict__ bw,
                               __half* __restrict__ out){
    int row = blockIdx.x;
    int tid = threadIdx.x;
    const float* yr = y + (size_t)row*CDIM;
    const float* zr = xz + (size_t)row*768 + 384;
    float v0 = yr[tid], v1 = yr[tid+128], v2 = yr[tid+256];
    float s = v0+v1+v2;
    float q = v0*v0 + v1*v1 + v2*v2;
    #pragma unroll
    for (int m = 16; m; m >>= 1){
        s += __shfl_xor_sync(0xffffffffu, s, m);
        q += __shfl_xor_sync(0xffffffffu, q, m);
    }
    __shared__ float red[8];
    if ((tid & 31) == 0){ red[tid>>5] = s; red[4 + (tid>>5)] = q; }
    __syncthreads();
    s = red[0]+red[1]+red[2]+red[3];
    q = red[4]+red[5]+red[6]+red[7];
    float mean = s * (1.f/CDIM);
    float var  = q * (1.f/CDIM) - mean*mean;
    float r = rsqrtf(var + 1e-6f);
    __half* orow = out + (size_t)row*CDIM;
    orow[tid]     = __float2half(((v0-mean)*r*gw[tid]     + bw[tid])     * siluf(zr[tid]));
    orow[tid+128] = __float2half(((v1-mean)*r*gw[tid+128] + bw[tid+128]) * siluf(zr[tid+128]));
    orow[tid+256] = __float2half(((v2-mean)*r*gw[tid+256] + bw[tid+256]) * siluf(zr[tid+256]));
}

// ---------------- fused precompute: conv-w layout + concatenated [wxp|wcomb] ----------------
__global__ void prep_kernel(const float* __restrict__ cw, float* __restrict__ wT,
                            const float* __restrict__ Wx, const float* __restrict__ Wdt,
                            __half* __restrict__ Wcat){
    int idx = blockIdx.x*256 + threadIdx.x;
    if (idx < 27*CDIM){
        int c = idx / 27, k = idx % 27;
        wT[k*CDIM + c] = cw[idx];
    }
    if (idx < CDIM*64){
        int i = idx >> 6, c = idx & 63;
        Wcat[(size_t)c*CDIM + i] = __float2half((c < 32) ? Wx[i*56 + 24 + c] : 0.f);
    }
    if (idx < CDIM*CDIM){
        int i = idx / CDIM, j = idx % CDIM;
        float s = 0.f;
        #pragma unroll
        for (int k = 0; k < DTRANK; k++) s = fmaf(Wx[i*56 + k], Wdt[k*CDIM + j], s);
        Wcat[(size_t)(64 + j)*CDIM + i] = __float2half(s);
    }
}

// batched weight transpose -> half
__global__ void wtransAll_kernel(const float* __restrict__ Win, const float* __restrict__ Wout,
                                 const float* __restrict__ W1, const float* __restrict__ W2,
                                 __half* __restrict__ winT, __half* __restrict__ woutT,
                                 __half* __restrict__ w1T, __half* __restrict__ w2T){
    __shared__ float t[32][33];
    int z = blockIdx.z;
    const float* in; __half* out; int R = 384, C;
    if (z == 0){ in = Win;  out = winT;  C = 768; }
    else if (z == 1){ in = Wout; out = woutT; C = 384; }
    else if (z == 2){ in = W1;   out = w1T;   C = 384; }
    else { in = W2; out = w2T; C = 384; }
    if (blockIdx.x * 32 >= C) return;
    int rb = blockIdx.y*32, cb = blockIdx.x*32;
    t[threadIdx.y][threadIdx.x] = in[(size_t)(rb+threadIdx.y)*C + cb + threadIdx.x];
    __syncthreads();
    out[(size_t)(cb+threadIdx.y)*R + rb + threadIdx.x] = __float2half(t[threadIdx.x][threadIdx.y]);
}

// generic fp32 [R][C] -> [C][R] transpose
__global__ void transpose_kernel(const float* __restrict__ in, float* __restrict__ out,
                                 int R, int C){
    __shared__ float t[32][33];
    int rb = blockIdx.y*32, cb = blockIdx.x*32;
    t[threadIdx.y][threadIdx.x] = in[(size_t)(rb+threadIdx.y)*C + cb + threadIdx.x];
    __syncthreads();
    out[(size_t)(cb+threadIdx.y)*R + rb + threadIdx.x] = t[threadIdx.x][threadIdx.y];
}

// ---------------- depthwise 3x3x3 conv + bias + SiLU (fp32 + half outs) ----------------
__global__ void conv_silu_kernel(const float* __restrict__ xz, const float* __restrict__ wT,
                                 const float* __restrict__ cb, float* __restrict__ out,
                                 __half* __restrict__ outh){
    int tok = blockIdx.x;
    int c   = threadIdx.x;
    int b = tok >> 11;
    int l = tok & 2047;
    int dd = l >> 8, hh = (l >> 4) & 15, ww = l & 15;
    float acc = cb[c];
    #pragma unroll
    for (int kd = 0; kd < 3; kd++){
        int d2 = dd + kd - 1;
        if ((unsigned)d2 >= 8u) continue;
        #pragma unroll
        for (int kh = 0; kh < 3; kh++){
            int h2 = hh + kh - 1;
            if ((unsigned)h2 >= 16u) continue;
            #pragma unroll
            for (int kw = 0; kw < 3; kw++){
                int w2 = ww + kw - 1;
                if ((unsigned)w2 >= 16u) continue;
                int l2 = (d2 << 8) + (h2 << 4) + w2;
                float xv = __ldg(xz + ((size_t)(b*2048 + l2))*768 + c);
                float wv = __ldg(wT + ((kd*3+kh)*3+kw)*CDIM + c);
                acc = fmaf(xv, wv, acc);
            }
        }
    }
    float v = siluf(acc);
    out [(size_t)tok*CDIM + c] = v;
    outh[(size_t)tok*CDIM + c] = __float2half(v);
}

// ---------------- fp16 mma.sync GEMM with cp.async 3-stage pipeline (R12 core) ----------------
// BM=64, BK=32, SP=40. BN=128: 8 warps 2m x 4n. BN=64: 4m x 2n.
// EPI: 0 plain fp32, 2 gelu->half, 3 +res->fp32, 4 plain->half,
//      5 cat: cols<64 -> dbcT fp32 transposed (no bias); cols>=64 -> softplus -> dtT fp32 transposed (bias)
__device__ __forceinline__ void mma_f16(float* d, const uint32_t* a, const uint32_t* b){
    asm volatile(
        "mma.sync.aligned.m16n8k16.row.col.f32.f16.f16.f32 "
        "{%0,%1,%2,%3}, {%4,%5,%6,%7}, {%8,%9}, {%0,%1,%2,%3};"
        : "+f"(d[0]), "+f"(d[1]), "+f"(d[2]), "+f"(d[3])
        : "r"(a[0]), "r"(a[1]), "r"(a[2]), "r"(a[3]), "r"(b[0]), "r"(b[1]));
}

template<int BN, int EPI>
__global__ void __launch_bounds__(256, 2)
hgemm(const __half* __restrict__ A, const __half* __restrict__ Bt,
      const float* __restrict__ bias, const float* __restrict__ res,
      void* __restrict__ Cout, int N){
    constexpr int BM = 64, BK = 32, NKT = 12, SP = 40;   // SP halves (80B row)
    constexpr int WARPS_N = (BN == 128) ? 4 : 2;
    constexpr int WM  = (BN == 128) ? 32 : 16;
    constexpr int NTM = WM/16;
    constexpr int ASTG = BM*SP;      // halves per A stage
    constexpr int BSTG = BN*SP;

    extern __shared__ __align__(16) char sm_[];
    const __half* As = (const __half*)sm_;
    const __half* Bs = (const __half*)(sm_ + 3*ASTG*2);
    uint32_t aBase = smem_u32(sm_);
    uint32_t bBase = aBase + 3*ASTG*2;

    int tid  = threadIdx.x;
    int lane = tid & 31, wid = tid >> 5;
    int wm = wid / WARPS_N, wn = wid % WARPS_N;
    int row0 = blockIdx.y * BM;
    int col0 = blockIdx.x * BN;

    float acc[NTM][4][4];
    #pragma unroll
    for (int i = 0; i < NTM; i++)
        #pragma unroll
        for (int j = 0; j < 4; j++)
            #pragma unroll
            for (int r = 0; r < 4; r++) acc[i][j][r] = 0.f;

    // cp.async source/dest mapping
    int arow = tid >> 2, acol = (tid & 3)*8;           // A: 64 rows, 8 halves/thread
    const __half* agp = A + (size_t)(row0 + arow)*CDIM + acol;
    uint32_t aoff = ((uint32_t)arow*SP + acol)*2;
    int brow, bcol;
    if (BN == 128){ brow = tid >> 1; bcol = (tid & 1)*16; }
    else          { brow = tid >> 2; bcol = (tid & 3)*8;  }
    const __half* bgp = Bt + (size_t)(col0 + brow)*CDIM + bcol;
    uint32_t boff = ((uint32_t)brow*SP + bcol)*2;

    auto issue = [&](int kt){
        int s = kt % 3;
        cp16(aBase + (uint32_t)s*ASTG*2 + aoff, agp + kt*BK);
        cp16(bBase + (uint32_t)s*BSTG*2 + boff, bgp + kt*BK);
        if (BN == 128)
            cp16(bBase + (uint32_t)s*BSTG*2 + boff + 16, bgp + kt*BK + 8);
    };

    issue(0); CP_COMMIT();
    issue(1); CP_COMMIT();

    for (int kt = 0; kt < NKT; kt++){
        if (kt >= NKT-2) { CP_WAIT(0); } else { CP_WAIT(1); }
        __syncthreads();
        int s = kt % 3;
        const __half* Ast = As + s*ASTG;
        const __half* Bst = Bs + s*BSTG;
        #pragma unroll
        for (int kb = 0; kb < 2; kb++){
            int kc = kb*16 + (lane & 3)*2;
            uint32_t a[NTM][4], b[4][2];
            #pragma unroll
            for (int mt = 0; mt < NTM; mt++){
                int mr = wm*WM + mt*16 + (lane>>2);
                a[mt][0] = *reinterpret_cast<const uint32_t*>(&Ast[mr*SP + kc]);
                a[mt][1] = *reinterpret_cast<const uint32_t*>(&Ast[(mr+8)*SP + kc]);
                a[mt][2] = *reinterpret_cast<const uint32_t*>(&Ast[mr*SP + kc + 8]);
                a[mt][3] = *reinterpret_cast<const uint32_t*>(&Ast[(mr+8)*SP + kc + 8]);
            }
            #pragma unroll
            for (int nt = 0; nt < 4; nt++){
                int nr = wn*32 + nt*8 + (lane>>2);
                b[nt][0] = *reinterpret_cast<const uint32_t*>(&Bst[nr*SP + kc]);
                b[nt][1] = *reinterpret_cast<const uint32_t*>(&Bst[nr*SP + kc + 8]);
            }
            #pragma unroll
            for (int mt = 0; mt < NTM; mt++)
                #pragma unroll
                for (int nt = 0; nt < 4; nt++)
                    mma_f16(acc[mt][nt], a[mt], b[nt]);
        }
        if (kt + 2 < NKT){ issue(kt+2); CP_COMMIT(); }
    }

    // epilogue
    #pragma unroll
    for (int mt = 0; mt < NTM; mt++){
        int r_ = row0 + wm*WM + mt*16 + (lane >> 2);
        #pragma unroll
        for (int nt = 0; nt < 4; nt++){
            int c_ = col0 + wn*32 + nt*8 + (lane & 3)*2;
            #pragma unroll
            for (int half_ = 0; half_ < 2; half_++){
                int rr = r_ + half_*8;
                float v0 = acc[mt][nt][half_*2+0];
                float v1 = acc[mt][nt][half_*2+1];
                if (EPI == 5){
                    if (c_ < 64){
                        float* C = (float*)Cout;       // dbcT [64][4096]
                        C[(size_t)c_*TOK + rr]     = v0;
                        C[(size_t)(c_+1)*TOK + rr] = v1;
                    } else {
                        float* D = (float*)res;        // dtT [384][4096]
                        int dc = c_ - 64;
                        D[(size_t)dc*TOK + rr]     = softplusf(v0 + bias[dc]);
                        D[(size_t)(dc+1)*TOK + rr] = softplusf(v1 + bias[dc+1]);
                    }
                    continue;
                }
                if (bias){ v0 += bias[c_]; v1 += bias[c_+1]; }
                if (EPI == 2){
                    __half* C = (__half*)Cout;
                    *reinterpret_cast<__half2*>(&C[(size_t)rr*N + c_]) =
                        __floats2half2_rn(geluf(v0), geluf(v1));
                } else if (EPI == 4){
                    __half* C = (__half*)Cout;
                    *reinterpret_cast<__half2*>(&C[(size_t)rr*N + c_]) =
                        __floats2half2_rn(v0, v1);
                } else {
                    float* C = (float*)Cout;
                    if (EPI == 3){
                        float2 rv = *reinterpret_cast<const float2*>(&res[(size_t)rr*N + c_]);
                        v0 += rv.x; v1 += rv.y;
                    }
                    float2 ov; ov.x = v0; ov.y = v1;
                    *reinterpret_cast<float2*>(&C[(size_t)rr*N + c_]) = ov;
                }
            }
        }
    }
}

// ---------------- chunk-parallel selective scan (all operands transposed) ----------------
// dtT[d][tok], xcT[d][tok], dbcT[s|32+s][tok]
__global__ void scan_pass1(const float* __restrict__ dtT, const float* __restrict__ xcT,
                           const float* __restrict__ dbcT, const float* __restrict__ A_log,
                           float* __restrict__ Pout, float* __restrict__ Sout){
    int tid = threadIdx.x;
    int s = tid & 15;
    int gid = blockIdx.x * 16 + (tid >> 4);
    int bd = gid >> 5;
    int chunk = gid & 31;
    int b = bd / CDIM;
    int d = bd % CDIM;
    int l0 = chunk * CLEN;

    float Ads = -__expf(A_log[d*DSTATE + s]);
    const float* dtp = dtT  + (size_t)d*TOK + b*LSEQ + l0;
    const float* xp  = xcT  + (size_t)d*TOK + b*LSEQ + l0;
    const float* bp  = dbcT + (size_t)s*TOK + b*LSEQ + l0;

    float P = 1.f, h = 0.f;
    #pragma unroll 4
    for (int l = 0; l < CLEN; l++){
        float dtv = __ldg(dtp + l);
        float xv  = __ldg(xp  + l);
        float Bv  = __ldg(bp  + l);
        float da  = __expf(dtv * Ads);
        h = fmaf(da, h, dtv * Bv * xv);
        P *= da;
    }
    Pout[(size_t)gid*DSTATE + s] = P;
    Sout[(size_t)gid*DSTATE + s] = h;
}

__global__ void scan_combine(const float* __restrict__ P, const float* __restrict__ S,
                             float* __restrict__ hs){
    int idx = blockIdx.x*256 + threadIdx.x;
    if (idx >= 768*DSTATE) return;
    int bd = idx >> 4;
    int s  = idx & 15;
    float h = 0.f;
    #pragma unroll
    for (int c = 0; c < NCHUNK; c++){
        size_t off = ((size_t)(bd*NCHUNK + c))*DSTATE + s;
        hs[off] = h;
        h = fmaf(P[off], h, S[off]);
    }
}

__global__ void scan_pass2(const float* __restrict__ dtT, const float* __restrict__ xcT,
                           const float* __restrict__ dbcT, const float* __restrict__ A_log,
                           const float* __restrict__ Dsk, const float* __restrict__ hs,
                           float* __restrict__ y){
    int tid = threadIdx.x;
    int s = tid & 15;
    int gid = blockIdx.x * 16 + (tid >> 4);
    int bd = gid >> 5;
    int chunk = gid & 31;
    int b = bd / CDIM;
    int d = bd % CDIM;
    int l0 = chunk * CLEN;

    float Ads   = -__expf(A_log[d*DSTATE + s]);
    float dskip = Dsk[d];
    float h = hs[(size_t)gid*DSTATE + s];

    const float* dtp = dtT  + (size_t)d*TOK + b*LSEQ + l0;
    const float* xp  = xcT  + (size_t)d*TOK + b*LSEQ + l0;
    const float* bp  = dbcT + (size_t)s*TOK + b*LSEQ + l0;
    const float* cp  = dbcT + (size_t)(32 + s)*TOK + b*LSEQ + l0;
    float* yp = y + ((size_t)b*LSEQ + l0)*CDIM + d;

    #pragma unroll 4
    for (int l = 0; l < CLEN; l++){
        float dtv = __ldg(dtp + l);
        float xv  = __ldg(xp  + l);
        float Bv  = __ldg(bp  + l);
        float Cv  = __ldg(cp  + l);
        float da  = __expf(dtv * Ads);
        h = fmaf(da, h, dtv * Bv * xv);
        float part = h * Cv;
        part += __shfl_xor_sync(0xffffffffu, part, 1);
        part += __shfl_xor_sync(0xffffffffu, part, 2);
        part += __shfl_xor_sync(0xffffffffu, part, 4);
        part += __shfl_xor_sync(0xffffffffu, part, 8);
        if (s == 0) yp[(size_t)l*CDIM] = part + xv * dskip;
    }
}

// ---------------- launcher ----------------
extern "C" void kernel_launch(void* const* d_in, const int* in_sizes, int n_in,
                              void* d_out, int out_size){
    const float* x      = (const float*)d_in[0];
    const float* g1     = (const float*)d_in[1];
    const float* b1     = (const float*)d_in[2];
    const float* W_in   = (const float*)d_in[3];
    const float* b_in   = (const float*)d_in[4];
    const float* conv_w = (const float*)d_in[5];
    const float* conv_b = (const float*)d_in[6];
    const float* W_x    = (const float*)d_in[7];
    const float* W_dt   = (const float*)d_in[8];
    const float* b_dt   = (const float*)d_in[9];
    const float* A_log  = (const float*)d_in[10];
    const float* Dsk    = (const float*)d_in[11];
    const float* on_g   = (const float*)d_in[12];
    const float* on_b   = (const float*)d_in[13];
    const float* W_out  = (const float*)d_in[14];
    const float* b_out  = (const float*)d_in[15];
    const float* g2     = (const float*)d_in[16];
    const float* b2     = (const float*)d_in[17];
    const float* W1     = (const float*)d_in[18];
    const float* b1m    = (const float*)d_in[19];
    const float* W2     = (const float*)d_in[20];
    const float* b2m    = (const float*)d_in[21];
    float* out = (float*)d_out;

    float *xz, *xc, *xcT, *dbcT, *dtT, *y, *x1, *wT, *P, *S, *hs;
    __half *hln_h, *xc_h, *y2_h, *h2_h, *t1_h;
    __half *winT, *wcatT, *woutT, *w1T, *w2T;
    cudaGetSymbolAddress((void**)&xz,  g_xz);
    cudaGetSymbolAddress((void**)&xc,  g_xc);
    cudaGetSymbolAddress((void**)&xcT, g_xcT);
    cudaGetSymbolAddress((void**)&dbcT, g_dbcT);
    cudaGetSymbolAddress((void**)&dtT, g_dtT);
    cudaGetSymbolAddress((void**)&y,   g_y);
    cudaGetSymbolAddress((void**)&x1,  g_x1);
    cudaGetSymbolAddress((void**)&wT,  g_wT);
    cudaGetSymbolAddress((void**)&hln_h, g_hln_h);
    cudaGetSymbolAddress((void**)&xc_h,  g_xc_h);
    cudaGetSymbolAddress((void**)&y2_h,  g_y2_h);
    cudaGetSymbolAddress((void**)&h2_h,  g_h2_h);
    cudaGetSymbolAddress((void**)&t1_h,  g_t1_h);
    cudaGetSymbolAddress((void**)&winT, g_winT);
    cudaGetSymbolAddress((void**)&wcatT, g_wcatT);
    cudaGetSymbolAddress((void**)&woutT, g_woutT);
    cudaGetSymbolAddress((void**)&w1T, g_w1T);
    cudaGetSymbolAddress((void**)&w2T, g_w2T);
    cudaGetSymbolAddress((void**)&P,   g_P);
    cudaGetSymbolAddress((void**)&S,   g_S);
    cudaGetSymbolAddress((void**)&hs,  g_hs);

    // dynamic smem: 3 stages * (A 64*40 + B BN*40) halves
    const int SM128 = 3*(64*40 + 128*40)*2;   // 46080
    const int SM64  = 3*(64*40 +  64*40)*2;   // 30720
    cudaFuncSetAttribute(hgemm<128,2>, cudaFuncAttributeMaxDynamicSharedMemorySize, SM128);
    cudaFuncSetAttribute(hgemm<128,3>, cudaFuncAttributeMaxDynamicSharedMemorySize, SM128);
    cudaFuncSetAttribute(hgemm<128,4>, cudaFuncAttributeMaxDynamicSharedMemorySize, SM128);
    cudaFuncSetAttribute(hgemm<128,0>, cudaFuncAttributeMaxDynamicSharedMemorySize, SM128);
    cudaFuncSetAttribute(hgemm<64,5>,  cudaFuncAttributeMaxDynamicSharedMemorySize, SM64);

    // precompute (2 launches)
    prep_kernel<<<576, 256>>>(conv_w, wT, W_x, W_dt, wcatT);
    wtransAll_kernel<<<dim3(24,12,4), dim3(32,32)>>>(W_in, W_out, W1, W2,
                                                     winT, woutT, w1T, w2T);

    // 1) hln = LN(x) (half)
    ln_kernel<<<TOK, 128>>>(x, g1, b1, hln_h);
    // 2) xz = hln @ W_in + b_in   [4096,768] fp32
    hgemm<128,0><<<dim3(6,64), 256, SM128>>>(hln_h, winT, b_in, nullptr, xz, 768);
    // 3) depthwise conv + SiLU -> xc (fp32) + xc_h (half); xcT for the scan
    conv_silu_kernel<<<TOK, CDIM>>>(xz, wT, conv_b, xc, xc_h);
    transpose_kernel<<<dim3(12,128), dim3(32,32)>>>(xc, xcT, TOK, CDIM);
    // 4+5) fused: [dbcT | dtT] = xc @ [wxp | wcomb]  (N=448, BN=64, both outputs transposed)
    hgemm<64,5><<<dim3(7,64), 256, SM64>>>(xc_h, wcatT, b_dt, dtT, dbcT, 448);
    // 6) chunk-parallel selective scan -> y (+ D_skip*xin)
    scan_pass1<<<1536, 256>>>(dtT, xcT, dbcT, A_log, P, S);
    scan_combine<<<48, 256>>>(P, S, hs);
    scan_pass2<<<1536, 256>>>(dtT, xcT, dbcT, A_log, Dsk, hs, y);
    // 7) y2 = LN(y)*silu(z) (half)
    ln_gate_kernel<<<TOK, 128>>>(y, xz, on_g, on_b, y2_h);
    // 8) x1 = x + y2 @ W_out + b_out (fp32)
    hgemm<128,3><<<dim3(3,64), 256, SM128>>>(y2_h, woutT, b_out, x, x1, 384);
    // 9) h2 = LN(x1) (half)
    ln_kernel<<<TOK, 128>>>(x1, g2, b2, h2_h);
    // 10) t1 = gelu(h2 @ W1 + b1m) (half)
    hgemm<128,2><<<dim3(3,64), 256, SM128>>>(h2_h, w1T, b1m, nullptr, t1_h, 384);
    // 11) out = x1 + t1 @ W2 + b2m (fp32)
    hgemm<128,3><<<dim3(3,64), 256, SM128>>>(t1_h, w2T, b2m, x1, out, 384);
}

// round 15
// speedup vs baseline: 2.4609x; 2.4609x over previous
#include <cuda_runtime.h>
#include <cuda_fp16.h>
#include <math.h>
#include <stdint.h>

// Problem constants
#define TOK 4096          // B * L = 2 * 2048
#define CDIM 384
#define LSEQ 2048
#define DSTATE 16
#define DTRANK 24
#define NCHUNK 32
#define CLEN 64           // LSEQ / NCHUNK

// ---------------- scratch (no cudaMalloc allowed) ----------------
__device__ float g_xz [TOK*768];
__device__ float g_xcT[CDIM*TOK];      // xc transposed [d][tok] (written by conv)
__device__ float g_dbc64[TOK*64];
__device__ float g_dtT[CDIM*TOK];      // dt transposed [d][tok], fp32 (feeds exp)
__device__ float g_y  [TOK*CDIM];
__device__ float g_x1 [TOK*CDIM];
__device__ float g_wT [27*CDIM];
// half activations (GEMM A operands)
__device__ __half g_hln_h[TOK*CDIM];
__device__ __half g_xc_h [TOK*CDIM];
__device__ __half g_y2_h [TOK*CDIM];
__device__ __half g_h2_h [TOK*CDIM];
__device__ __half g_t1_h [TOK*CDIM];
// half transposed weights [N][K=384], K-major
__device__ __half g_winT [768*CDIM];
__device__ __half g_wcombT[CDIM*CDIM];
__device__ __half g_wxpT [64*CDIM];
__device__ __half g_woutT[CDIM*CDIM];
__device__ __half g_w1T  [CDIM*CDIM];
__device__ __half g_w2T  [CDIM*CDIM];

// ---------------- math helpers ----------------
__device__ __forceinline__ float siluf(float x){ return x / (1.f + __expf(-x)); }
__device__ __forceinline__ float geluf(float x){
    float x3 = x*x*x;
    return 0.5f*x*(1.f + tanhf(0.7978845608028654f*(x + 0.044715f*x3)));
}
__device__ __forceinline__ float softplusf(float x){
    return fmaxf(x, 0.f) + log1pf(__expf(-fabsf(x)));
}
__device__ __forceinline__ uint32_t smem_u32(const void* p){
    uint32_t a;
    asm("{ .reg .u64 t; cvta.to.shared.u64 t, %1; cvt.u32.u64 %0, t; }" : "=r"(a) : "l"(p));
    return a;
}
__device__ __forceinline__ void cp16(uint32_t saddr, const void* g){
    asm volatile("cp.async.cg.shared.global [%0], [%1], 16;" :: "r"(saddr), "l"(g));
}
#define CP_COMMIT() asm volatile("cp.async.commit_group;")
#define CP_WAIT(n)  asm volatile("cp.async.wait_group %0;" :: "n"(n))

// ---------------- LayerNorm over C=384 (half output for GEMM A) ----------------
__global__ void ln_kernel(const float* __restrict__ x, const float* __restrict__ gw,
                          const float* __restrict__ bw, __half* __restrict__ out){
    int row = blockIdx.x;
    int tid = threadIdx.x;
    const float* xr = x + (size_t)row*CDIM;
    float v0 = xr[tid], v1 = xr[tid+128], v2 = xr[tid+256];
    float s = v0+v1+v2;
    float q = v0*v0 + v1*v1 + v2*v2;
    #pragma unroll
    for (int m = 16; m; m >>= 1){
        s += __shfl_xor_sync(0xffffffffu, s, m);
        q += __shfl_xor_sync(0xffffffffu, q, m);
    }
    __shared__ float red[8];
    if ((tid & 31) == 0){ red[tid>>5] = s; red[4 + (tid>>5)] = q; }
    __syncthreads();
    s = red[0]+red[1]+red[2]+red[3];
    q = red[4]+red[5]+red[6]+red[7];
    float mean = s * (1.f/CDIM);
    float var  = q * (1.f/CDIM) - mean*mean;
    float r = rsqrtf(var + 1e-6f);
    __half* orow = out + (size_t)row*CDIM;
    orow[tid]     = __float2half((v0-mean)*r*gw[tid]     + bw[tid]);
    orow[tid+128] = __float2half((v1-mean)*r*gw[tid+128] + bw[tid+128]);
    orow[tid+256] = __float2half((v2-mean)*r*gw[tid+256] + bw[tid+256]);
}

__global__ void ln_gate_kernel(const float* __restrict__ y, const float* __restrict__ xz,
                               const float* __restrict__ gw, const float* __restrict__ bw,
                               __half* __restrict__ out){
    int row = blockIdx.x;
    int tid = threadIdx.x;
    const float* yr = y + (size_t)row*CDIM;
    const float* zr = xz + (size_t)row*768 + 384;
    float v0 = yr[tid], v1 = yr[tid+128], v2 = yr[tid+256];
    float s = v0+v1+v2;
    float q = v0*v0 + v1*v1 + v2*v2;
    #pragma unroll
    for (int m = 16; m; m >>= 1){
        s += __shfl_xor_sync(0xffffffffu, s, m);
        q += __shfl_xor_sync(0xffffffffu, q, m);
    }
    __shared__ float red[8];
    if ((tid & 31) == 0){ red[tid>>5] = s; red[4 + (tid>>5)] = q; }
    __syncthreads();
    s = red[0]+red[1]+red[2]+red[3];
    q = red[4]+red[5]+red[6]+red[7];
    float mean = s * (1.f/CDIM);
    float var  = q * (1.f/CDIM) - mean*mean;
    float r = rsqrtf(var + 1e-6f);
    __half* orow = out + (size_t)row*CDIM;
    orow[tid]     = __float2half(((v0-mean)*r*gw[tid]     + bw[tid])     * siluf(zr[tid]));
    orow[tid+128] = __float2half(((v1-mean)*r*gw[tid+128] + bw[tid+128]) * siluf(zr[tid+128]));
    orow[tid+256] = __float2half(((v2-mean)*r*gw[tid+256] + bw[tid+256]) * siluf(zr[tid+256]));
}

// ---------------- fused precompute: conv-w layout, wcombT(h), wxpT(h) ----------------
__global__ void prep_kernel(const float* __restrict__ cw, float* __restrict__ wT,
                            const float* __restrict__ Wx, const float* __restrict__ Wdt,
                            __half* __restrict__ WcT, __half* __restrict__ Wp){
    int idx = blockIdx.x*256 + threadIdx.x;
    if (idx < 27*CDIM){
        int c = idx / 27, k = idx % 27;
        wT[k*CDIM + c] = cw[idx];
    }
    if (idx < CDIM*64){
        int i = idx >> 6, c = idx & 63;
        Wp[c*CDIM + i] = __float2half((c < 32) ? Wx[i*56 + 24 + c] : 0.f);
    }
    if (idx < CDIM*CDIM){
        int i = idx / CDIM, j = idx % CDIM;
        float s = 0.f;
        #pragma unroll
        for (int k = 0; k < DTRANK; k++) s = fmaf(Wx[i*56 + k], Wdt[k*CDIM + j], s);
        WcT[j*CDIM + i] = __float2half(s);
    }
}

// batched weight transpose -> half: z=0 W_in(384x768), z=1..3 W_out/W1/W2 (384x384)
__global__ void wtransAll_kernel(const float* __restrict__ Win, const float* __restrict__ Wout,
                                 const float* __restrict__ W1, const float* __restrict__ W2,
                                 __half* __restrict__ winT, __half* __restrict__ woutT,
                                 __half* __restrict__ w1T, __half* __restrict__ w2T){
    __shared__ float t[32][33];
    int z = blockIdx.z;
    const float* in; __half* out; int R = 384, C;
    if (z == 0){ in = Win;  out = winT;  C = 768; }
    else if (z == 1){ in = Wout; out = woutT; C = 384; }
    else if (z == 2){ in = W1;   out = w1T;   C = 384; }
    else { in = W2; out = w2T; C = 384; }
    if (blockIdx.x * 32 >= C) return;
    int rb = blockIdx.y*32, cb = blockIdx.x*32;
    t[threadIdx.y][threadIdx.x] = in[(size_t)(rb+threadIdx.y)*C + cb + threadIdx.x];
    __syncthreads();
    out[(size_t)(cb+threadIdx.y)*R + rb + threadIdx.x] = __float2half(t[threadIdx.x][threadIdx.y]);
}

// ---------------- depthwise 3x3x3 conv + bias + SiLU -> xcT (fp32) + xc_h (half) ----------------
__global__ void conv_silu_kernel(const float* __restrict__ xz, const float* __restrict__ wT,
                                 const float* __restrict__ cb, float* __restrict__ outT,
                                 __half* __restrict__ outh){
    int tok = blockIdx.x;
    int c   = threadIdx.x;
    int b = tok >> 11;
    int l = tok & 2047;
    int dd = l >> 8, hh = (l >> 4) & 15, ww = l & 15;
    float acc = cb[c];
    #pragma unroll
    for (int kd = 0; kd < 3; kd++){
        int d2 = dd + kd - 1;
        if ((unsigned)d2 >= 8u) continue;
        #pragma unroll
        for (int kh = 0; kh < 3; kh++){
            int h2 = hh + kh - 1;
            if ((unsigned)h2 >= 16u) continue;
            #pragma unroll
            for (int kw = 0; kw < 3; kw++){
                int w2 = ww + kw - 1;
                if ((unsigned)w2 >= 16u) continue;
                int l2 = (d2 << 8) + (h2 << 4) + w2;
                float xv = __ldg(xz + ((size_t)(b*2048 + l2))*768 + c);
                float wv = __ldg(wT + ((kd*3+kh)*3+kw)*CDIM + c);
                acc = fmaf(xv, wv, acc);
            }
        }
    }
    float v = siluf(acc);
    outT[(size_t)c*TOK + tok]  = v;              // transposed, for the scan
    outh[(size_t)tok*CDIM + c] = __float2half(v); // row-major half, GEMM A operand
}

// ---------------- fp16 mma.sync GEMM with cp.async 3-stage pipeline (R12 core) ----------------
// BM=64, BK=32, SP=40. BN=128: 8 warps 2m x 4n. BN=64: 4m x 2n.
// EPI: 0 plain fp32, 1 softplus + TRANSPOSED store (dtT[col][row]), 2 gelu->half, 3 +res fp32, 4 plain->half
__device__ __forceinline__ void mma_f16(float* d, const uint32_t* a, const uint32_t* b){
    asm volatile(
        "mma.sync.aligned.m16n8k16.row.col.f32.f16.f16.f32 "
        "{%0,%1,%2,%3}, {%4,%5,%6,%7}, {%8,%9}, {%0,%1,%2,%3};"
        : "+f"(d[0]), "+f"(d[1]), "+f"(d[2]), "+f"(d[3])
        : "r"(a[0]), "r"(a[1]), "r"(a[2]), "r"(a[3]), "r"(b[0]), "r"(b[1]));
}

template<int BN, int EPI>
__global__ void __launch_bounds__(256, 2)
hgemm(const __half* __restrict__ A, const __half* __restrict__ Bt,
      const float* __restrict__ bias, const float* __restrict__ res,
      void* __restrict__ Cout, int N){
    constexpr int BM = 64, BK = 32, NKT = 12, SP = 40;   // SP halves (80B row)
    constexpr int WARPS_N = (BN == 128) ? 4 : 2;
    constexpr int WM  = (BN == 128) ? 32 : 16;
    constexpr int NTM = WM/16;
    constexpr int ASTG = BM*SP;      // halves per A stage
    constexpr int BSTG = BN*SP;

    extern __shared__ __align__(16) char sm_[];
    const __half* As = (const __half*)sm_;
    const __half* Bs = (const __half*)(sm_ + 3*ASTG*2);
    uint32_t aBase = smem_u32(sm_);
    uint32_t bBase = aBase + 3*ASTG*2;

    int tid  = threadIdx.x;
    int lane = tid & 31, wid = tid >> 5;
    int wm = wid / WARPS_N, wn = wid % WARPS_N;
    int row0 = blockIdx.y * BM;
    int col0 = blockIdx.x * BN;

    float acc[NTM][4][4];
    #pragma unroll
    for (int i = 0; i < NTM; i++)
        #pragma unroll
        for (int j = 0; j < 4; j++)
            #pragma unroll
            for (int r = 0; r < 4; r++) acc[i][j][r] = 0.f;

    // cp.async source/dest mapping
    int arow = tid >> 2, acol = (tid & 3)*8;           // A: 64 rows, 8 halves/thread
    const __half* agp = A + (size_t)(row0 + arow)*CDIM + acol;
    uint32_t aoff = ((uint32_t)arow*SP + acol)*2;
    int brow, bcol;
    if (BN == 128){ brow = tid >> 1; bcol = (tid & 1)*16; }
    else          { brow = tid >> 2; bcol = (tid & 3)*8;  }
    const __half* bgp = Bt + (size_t)(col0 + brow)*CDIM + bcol;
    uint32_t boff = ((uint32_t)brow*SP + bcol)*2;

    auto issue = [&](int kt){
        int s = kt % 3;
        cp16(aBase + (uint32_t)s*ASTG*2 + aoff, agp + kt*BK);
        cp16(bBase + (uint32_t)s*BSTG*2 + boff, bgp + kt*BK);
        if (BN == 128)
            cp16(bBase + (uint32_t)s*BSTG*2 + boff + 16, bgp + kt*BK + 8);
    };

    issue(0); CP_COMMIT();
    issue(1); CP_COMMIT();

    for (int kt = 0; kt < NKT; kt++){
        if (kt >= NKT-2) { CP_WAIT(0); } else { CP_WAIT(1); }
        __syncthreads();
        int s = kt % 3;
        const __half* Ast = As + s*ASTG;
        const __half* Bst = Bs + s*BSTG;
        #pragma unroll
        for (int kb = 0; kb < 2; kb++){
            int kc = kb*16 + (lane & 3)*2;
            uint32_t a[NTM][4], b[4][2];
            #pragma unroll
            for (int mt = 0; mt < NTM; mt++){
                int mr = wm*WM + mt*16 + (lane>>2);
                a[mt][0] = *reinterpret_cast<const uint32_t*>(&Ast[mr*SP + kc]);
                a[mt][1] = *reinterpret_cast<const uint32_t*>(&Ast[(mr+8)*SP + kc]);
                a[mt][2] = *reinterpret_cast<const uint32_t*>(&Ast[mr*SP + kc + 8]);
                a[mt][3] = *reinterpret_cast<const uint32_t*>(&Ast[(mr+8)*SP + kc + 8]);
            }
            #pragma unroll
            for (int nt = 0; nt < 4; nt++){
                int nr = wn*32 + nt*8 + (lane>>2);
                b[nt][0] = *reinterpret_cast<const uint32_t*>(&Bst[nr*SP + kc]);
                b[nt][1] = *reinterpret_cast<const uint32_t*>(&Bst[nr*SP + kc + 8]);
            }
            #pragma unroll
            for (int mt = 0; mt < NTM; mt++)
                #pragma unroll
                for (int nt = 0; nt < 4; nt++)
                    mma_f16(acc[mt][nt], a[mt], b[nt]);
        }
        if (kt + 2 < NKT){ issue(kt+2); CP_COMMIT(); }
    }

    // epilogue
    #pragma unroll
    for (int mt = 0; mt < NTM; mt++){
        int r_ = row0 + wm*WM + mt*16 + (lane >> 2);
        #pragma unroll
        for (int nt = 0; nt < 4; nt++){
            int c_ = col0 + wn*32 + nt*8 + (lane & 3)*2;
            #pragma unroll
            for (int half_ = 0; half_ < 2; half_++){
                int rr = r_ + half_*8;
                float v0 = acc[mt][nt][half_*2+0];
                float v1 = acc[mt][nt][half_*2+1];
                if (bias){ v0 += bias[c_]; v1 += bias[c_+1]; }
                if (EPI == 1){
                    // softplus + transposed store: C is dtT[384][4096]
                    float* C = (float*)Cout;
                    C[(size_t)c_*TOK + rr]     = softplusf(v0);
                    C[(size_t)(c_+1)*TOK + rr] = softplusf(v1);
                    continue;
                }
                if (EPI == 2){
                    __half* C = (__half*)Cout;
                    *reinterpret_cast<__half2*>(&C[(size_t)rr*N + c_]) =
                        __floats2half2_rn(geluf(v0), geluf(v1));
                } else if (EPI == 4){
                    __half* C = (__half*)Cout;
                    *reinterpret_cast<__half2*>(&C[(size_t)rr*N + c_]) =
                        __floats2half2_rn(v0, v1);
                } else {
                    float* C = (float*)Cout;
                    if (EPI == 3){
                        float2 rv = *reinterpret_cast<const float2*>(&res[(size_t)rr*N + c_]);
                        v0 += rv.x; v1 += rv.y;
                    }
                    float2 ov; ov.x = v0; ov.y = v1;
                    *reinterpret_cast<float2*>(&C[(size_t)rr*N + c_]) = ov;
                }
            }
        }
    }
}

// ---------------- fused single-kernel selective scan ----------------
// One block per (b,d): 512 threads = 32 chunks x 16 states.
// dt/xc rows cached in smem once; chunk combine = in-block Hillis-Steele over (P,S).
__global__ void __launch_bounds__(512)
scan_fused(const float* __restrict__ dtT, const float* __restrict__ xcT,
           const float* __restrict__ dbc, const float* __restrict__ A_log,
           const float* __restrict__ Dsk, float* __restrict__ y){
    __shared__ float s_dt[LSEQ];
    __shared__ float s_x [LSEQ];
    __shared__ float sP[512];
    __shared__ float sS[512];

    int bd = blockIdx.x;            // 0..767
    int b = bd / CDIM;
    int d = bd % CDIM;
    int tid = threadIdx.x;
    int chunk = tid >> 4;
    int s = tid & 15;

    // cooperative row load (coalesced float4)
    const float4* dt4 = reinterpret_cast<const float4*>(dtT + (size_t)d*TOK + b*LSEQ);
    const float4* x4  = reinterpret_cast<const float4*>(xcT + (size_t)d*TOK + b*LSEQ);
    reinterpret_cast<float4*>(s_dt)[tid] = dt4[tid];
    reinterpret_cast<float4*>(s_x )[tid] = x4[tid];
    __syncthreads();

    float Ads = -__expf(A_log[d*DSTATE + s]);
    int l0 = chunk * CLEN;
    const float* bp = dbc + ((size_t)b*LSEQ + l0)*64 + s;
    const float* cp = bp + 32;

    // pass 1: per-chunk decay product P and local end state S (h0 = 0)
    float Pv = 1.f, h = 0.f;
    #pragma unroll 4
    for (int l = 0; l < CLEN; l++){
        float dtv = s_dt[l0 + l];
        float xv  = s_x [l0 + l];
        float Bv  = __ldg(bp + (size_t)l*64);
        float da  = __expf(dtv * Ads);
        h = fmaf(da, h, dtv * Bv * xv);
        Pv *= da;
    }
    sP[tid] = Pv; sS[tid] = h;
    __syncthreads();

    // inclusive Hillis-Steele scan over the chunk axis of affine pairs (P,S)
    #pragma unroll
    for (int off = 1; off < NCHUNK; off <<= 1){
        float p2 = sP[tid], s2 = sS[tid];
        float p1 = 0.f, s1 = 0.f;
        bool act = (chunk >= off);
        if (act){ p1 = sP[tid - off*16]; s1 = sS[tid - off*16]; }
        __syncthreads();
        if (act){ sP[tid] = p1 * p2; sS[tid] = fmaf(p2, s1, s2); }
        __syncthreads();
    }
    float hstart = (chunk == 0) ? 0.f : sS[(chunk-1)*16 + s];

    // pass 2: re-scan chunk from hstart, emit y
    float dskip = Dsk[d];
    h = hstart;
    float* yp = y + ((size_t)b*LSEQ + l0)*CDIM + d;
    #pragma unroll 4
    for (int l = 0; l < CLEN; l++){
        float dtv = s_dt[l0 + l];
        float xv  = s_x [l0 + l];
        float Bv  = __ldg(bp + (size_t)l*64);
        float Cv  = __ldg(cp + (size_t)l*64);
        float da  = __expf(dtv * Ads);
        h = fmaf(da, h, dtv * Bv * xv);
        float part = h * Cv;
        part += __shfl_xor_sync(0xffffffffu, part, 1);
        part += __shfl_xor_sync(0xffffffffu, part, 2);
        part += __shfl_xor_sync(0xffffffffu, part, 4);
        part += __shfl_xor_sync(0xffffffffu, part, 8);
        if (s == 0) yp[(size_t)l*CDIM] = part + xv * dskip;
    }
}

// ---------------- launcher ----------------
extern "C" void kernel_launch(void* const* d_in, const int* in_sizes, int n_in,
                              void* d_out, int out_size){
    const float* x      = (const float*)d_in[0];
    const float* g1     = (const float*)d_in[1];
    const float* b1     = (const float*)d_in[2];
    const float* W_in   = (const float*)d_in[3];
    const float* b_in   = (const float*)d_in[4];
    const float* conv_w = (const float*)d_in[5];
    const float* conv_b = (const float*)d_in[6];
    const float* W_x    = (const float*)d_in[7];
    const float* W_dt   = (const float*)d_in[8];
    const float* b_dt   = (const float*)d_in[9];
    const float* A_log  = (const float*)d_in[10];
    const float* Dsk    = (const float*)d_in[11];
    const float* on_g   = (const float*)d_in[12];
    const float* on_b   = (const float*)d_in[13];
    const float* W_out  = (const float*)d_in[14];
    const float* b_out  = (const float*)d_in[15];
    const float* g2     = (const float*)d_in[16];
    const float* b2     = (const float*)d_in[17];
    const float* W1     = (const float*)d_in[18];
    const float* b1m    = (const float*)d_in[19];
    const float* W2     = (const float*)d_in[20];
    const float* b2m    = (const float*)d_in[21];
    float* out = (float*)d_out;

    float *xz, *xcT, *dbc, *dtT, *y, *x1, *wT;
    __half *hln_h, *xc_h, *y2_h, *h2_h, *t1_h;
    __half *winT, *wcbT, *wxpT, *woutT, *w1T, *w2T;
    cudaGetSymbolAddress((void**)&xz,  g_xz);
    cudaGetSymbolAddress((void**)&xcT, g_xcT);
    cudaGetSymbolAddress((void**)&dbc, g_dbc64);
    cudaGetSymbolAddress((void**)&dtT, g_dtT);
    cudaGetSymbolAddress((void**)&y,   g_y);
    cudaGetSymbolAddress((void**)&x1,  g_x1);
    cudaGetSymbolAddress((void**)&wT,  g_wT);
    cudaGetSymbolAddress((void**)&hln_h, g_hln_h);
    cudaGetSymbolAddress((void**)&xc_h,  g_xc_h);
    cudaGetSymbolAddress((void**)&y2_h,  g_y2_h);
    cudaGetSymbolAddress((void**)&h2_h,  g_h2_h);
    cudaGetSymbolAddress((void**)&t1_h,  g_t1_h);
    cudaGetSymbolAddress((void**)&winT, g_winT);
    cudaGetSymbolAddress((void**)&wcbT, g_wcombT);
    cudaGetSymbolAddress((void**)&wxpT, g_wxpT);
    cudaGetSymbolAddress((void**)&woutT, g_woutT);
    cudaGetSymbolAddress((void**)&w1T, g_w1T);
    cudaGetSymbolAddress((void**)&w2T, g_w2T);

    // dynamic smem: 3 stages * (A 64*40 + B BN*40) halves
    const int SM128 = 3*(64*40 + 128*40)*2;   // 46080
    const int SM64  = 3*(64*40 +  64*40)*2;   // 30720
    cudaFuncSetAttribute(hgemm<128,0>, cudaFuncAttributeMaxDynamicSharedMemorySize, SM128);
    cudaFuncSetAttribute(hgemm<128,1>, cudaFuncAttributeMaxDynamicSharedMemorySize, SM128);
    cudaFuncSetAttribute(hgemm<128,2>, cudaFuncAttributeMaxDynamicSharedMemorySize, SM128);
    cudaFuncSetAttribute(hgemm<128,3>, cudaFuncAttributeMaxDynamicSharedMemorySize, SM128);
    cudaFuncSetAttribute(hgemm<64,0>,  cudaFuncAttributeMaxDynamicSharedMemorySize, SM64);

    // precompute (2 launches)
    prep_kernel<<<576, 256>>>(conv_w, wT, W_x, W_dt, wcbT, wxpT);
    wtransAll_kernel<<<dim3(24,12,4), dim3(32,32)>>>(W_in, W_out, W1, W2,
                                                     winT, woutT, w1T, w2T);

    // 1) hln = LN(x) (half)
    ln_kernel<<<TOK, 128>>>(x, g1, b1, hln_h);
    // 2) xz = hln @ W_in + b_in   [4096,768] fp32
    hgemm<128,0><<<dim3(6,64), 256, SM128>>>(hln_h, winT, b_in, nullptr, xz, 768);
    // 3) depthwise conv + SiLU -> xcT (fp32, transposed) + xc_h (half)
    conv_silu_kernel<<<TOK, CDIM>>>(xz, wT, conv_b, xcT, xc_h);
    // 4) dbc = xc @ wxp      [4096,64] fp32
    hgemm<64,0><<<dim3(1,64), 256, SM64>>>(xc_h, wxpT, nullptr, nullptr, dbc, 64);
    // 5) dtT = softplus(xc @ W_comb + b_dt)^T   [384,4096] fp32
    hgemm<128,1><<<dim3(3,64), 256, SM128>>>(xc_h, wcbT, b_dt, nullptr, dtT, 384);
    // 6) fused chunk-parallel selective scan -> y (+ D_skip*xin)
    scan_fused<<<768, 512>>>(dtT, xcT, dbc, A_log, Dsk, y);
    // 7) y2 = LN(y)*silu(z) (half)
    ln_gate_kernel<<<TOK, 128>>>(y, xz, on_g, on_b, y2_h);
    // 8) x1 = x + y2 @ W_out + b_out (fp32)
    hgemm<128,3><<<dim3(3,64), 256, SM128>>>(y2_h, woutT, b_out, x, x1, 384);
    // 9) h2 = LN(x1) (half)
    ln_kernel<<<TOK, 128>>>(x1, g2, b2, h2_h);
    // 10) t1 = gelu(h2 @ W1 + b1m) (half)
    hgemm<128,2><<<dim3(3,64), 256, SM128>>>(h2_h, w1T, b1m, nullptr, t1_h, 384);
    // 11) out = x1 + t1 @ W2 + b2m (fp32)
    hgemm<128,3><<<dim3(3,64), 256, SM128>>>(t1_h, w2T, b2m, x1, out, 384);
}